// round 5
// baseline (speedup 1.0000x reference)
#include <cuda_runtime.h>
#include <cuda_bf16.h>

// Problem constants (B=8, T=4096, C=512)
#define B_DIM 8
#define T_DIM 4096
#define C_DIM 512
#define NWARPS 32                  // warps per block, each owns one T-segment
#define SEG    (T_DIM / NWARPS)    // 128 timesteps per warp segment
#define NSUB   4                   // independent sub-streams per warp (ILP)
#define SUBLEN (SEG / NSUB)        // 32 timesteps per sub-stream
#define CT     32                  // channels per block (lane = channel)

// one recurrence step: h = A*h + x  (complex diag, x real)
__device__ __forceinline__ void step(float& hr, float& hi, float Ar, float Ai, float xv) {
    float nr = fmaf(hr, Ar, fmaf(-hi, Ai, xv));
    float ni = fmaf(hr, Ai, hi * Ar);
    hr = nr; hi = ni;
}

// e = p * e + l   (complex fma)
__device__ __forceinline__ void cfma(float& er, float& ei, float pr, float pi,
                                     float lr, float li) {
    float nr = fmaf(pr, er, fmaf(-pi, ei, lr));
    float ni = fmaf(pr, ei, fmaf(pi, er, li));
    er = nr; ei = ni;
}

__global__ __launch_bounds__(NWARPS * 32, 1)
void stateful_recurrent_kernel(const float* __restrict__ x,
                               const float* __restrict__ Ar_g,
                               const float* __restrict__ Ai_g,
                               const float* __restrict__ h0r_g,
                               const float* __restrict__ h0i_g,
                               float* __restrict__ out) {
    __shared__ float s_lr[NWARPS][CT];   // segment-local (zero-start) final real
    __shared__ float s_li[NWARPS][CT];
    __shared__ float s_sr[NWARPS][CT];   // segment-start real
    __shared__ float s_si[NWARPS][CT];

    const int lane  = threadIdx.x & 31;
    const int w     = threadIdx.x >> 5;
    const int b     = blockIdx.x >> 4;
    const int ctile = blockIdx.x & 15;
    const int c     = ctile * CT + lane;

    const float Ar = Ar_g[c];
    const float Ai = Ai_g[c];

    // A^SUBLEN = A^32 via 5 squarings
    float p32r = Ar, p32i = Ai;
    #pragma unroll
    for (int s = 0; s < 5; s++) {
        float nr = p32r * p32r - p32i * p32i;
        float ni = 2.f * p32r * p32i;
        p32r = nr; p32i = ni;
    }

    const float* xp = x + (size_t)b * T_DIM * C_DIM + c;
    const int t0 = w * SEG;

    // ------------- Phase A: 4 independent zero-start sub-scans (ILP=4) -------------
    float hr[NSUB], hi[NSUB];
    #pragma unroll
    for (int s = 0; s < NSUB; s++) { hr[s] = 0.f; hi[s] = 0.f; }

    for (int j = 0; j < SUBLEN; j += 2) {
        float xv[2 * NSUB];
        #pragma unroll
        for (int s = 0; s < NSUB; s++) {
            int t = t0 + s * SUBLEN + j;
            xv[s]        = xp[(size_t)t * C_DIM];
            xv[NSUB + s] = xp[(size_t)(t + 1) * C_DIM];
        }
        #pragma unroll
        for (int s = 0; s < NSUB; s++) step(hr[s], hi[s], Ar, Ai, xv[s]);
        #pragma unroll
        for (int s = 0; s < NSUB; s++) step(hr[s], hi[s], Ar, Ai, xv[NSUB + s]);
    }

    // combine 4 sub-finals -> segment-local final (Horner over A^32)
    {
        float er = hr[0], ei = hi[0];
        #pragma unroll
        for (int s = 1; s < NSUB; s++) cfma(er, ei, p32r, p32i, hr[s], hi[s]);
        s_lr[w][lane] = er;
        s_li[w][lane] = ei;
    }
    __syncthreads();

    // ------------- Phase B: serial combine over 32 segments (warp 0) -------------
    if (w == 0) {
        // A^SEG = (A^32)^4 via 2 more squarings
        float pr = p32r, pi = p32i;
        #pragma unroll
        for (int s = 0; s < 2; s++) {
            float nr = pr * pr - pi * pi;
            float ni = 2.f * pr * pi;
            pr = nr; pi = ni;
        }
        float cr = h0r_g[(size_t)b * C_DIM + c];
        float ci = h0i_g[(size_t)b * C_DIM + c];
        #pragma unroll 4
        for (int s = 0; s < NWARPS; s++) {
            s_sr[s][lane] = cr;
            s_si[s][lane] = ci;
            cfma(cr, ci, pr, pi, s_lr[s][lane], s_li[s][lane]);
        }
    }
    __syncthreads();

    // ------------- Phase C prep: derive the 4 sub-stream start states -------------
    // sub-start[0] = segment start; sub-start[s] = A^32 * sub-start[s-1] + local[s-1]
    {
        float sr = s_sr[w][lane];
        float si = s_si[w][lane];
        float nhr[NSUB], nhi[NSUB];
        nhr[0] = sr; nhi[0] = si;
        #pragma unroll
        for (int s = 1; s < NSUB; s++) {
            float er = nhr[s - 1], ei = nhi[s - 1];
            cfma(er, ei, p32r, p32i, hr[s - 1], hi[s - 1]);
            nhr[s] = er; nhi[s] = ei;
        }
        #pragma unroll
        for (int s = 0; s < NSUB; s++) { hr[s] = nhr[s]; hi[s] = nhi[s]; }
    }

    // ------------- Phase C: 4 interleaved replay streams, write out -------------
    float2* op = reinterpret_cast<float2*>(out) + (size_t)b * T_DIM * C_DIM + c;
    for (int j = 0; j < SUBLEN; j += 2) {
        float xv[2 * NSUB];
        #pragma unroll
        for (int s = 0; s < NSUB; s++) {
            int t = t0 + s * SUBLEN + j;
            xv[s]        = xp[(size_t)t * C_DIM];
            xv[NSUB + s] = xp[(size_t)(t + 1) * C_DIM];
        }
        #pragma unroll
        for (int s = 0; s < NSUB; s++) {
            int t = t0 + s * SUBLEN + j;
            step(hr[s], hi[s], Ar, Ai, xv[s]);
            op[(size_t)t * C_DIM] = make_float2(hr[s], hi[s]);
        }
        #pragma unroll
        for (int s = 0; s < NSUB; s++) {
            int t = t0 + s * SUBLEN + j + 1;
            step(hr[s], hi[s], Ar, Ai, xv[NSUB + s]);
            op[(size_t)t * C_DIM] = make_float2(hr[s], hi[s]);
        }
    }
}

extern "C" void kernel_launch(void* const* d_in, const int* in_sizes, int n_in,
                              void* d_out, int out_size) {
    const float* x   = (const float*)d_in[0];   // (B, T, C)
    const float* Ar  = (const float*)d_in[1];   // (C,)
    const float* Ai  = (const float*)d_in[2];   // (C,)
    const float* h0r = (const float*)d_in[3];   // (B, C)
    const float* h0i = (const float*)d_in[4];   // (B, C)
    float* out = (float*)d_out;                 // (B, T, C, 2)

    dim3 grid(B_DIM * (C_DIM / CT));            // 128 blocks
    dim3 block(NWARPS * 32);                    // 1024 threads
    stateful_recurrent_kernel<<<grid, block>>>(x, Ar, Ai, h0r, h0i, out);
}